// round 12
// baseline (speedup 1.0000x reference)
#include <cuda_runtime.h>
#include <cstdint>

#define NU_  100000
#define NI_  100000
#define NE_  600000
#define FU_  96
#define FI_  160
#define HH   128
#define OUTD 64
#define LN_EPS 1e-5f

// ---------------- scratch (device globals; no runtime allocation) ----------------
__device__ float g_hu  [NU_ * HH];
__device__ float g_hi  [NI_ * HH];
__device__ float g_hu1 [NU_ * HH];
__device__ float g_hi1 [NI_ * HH];
__device__ int   g_cntu[NU_];
__device__ int   g_cnti[NI_];
__device__ int   g_offu[NU_];
__device__ int   g_offi[NI_];
__device__ int   g_curu[NU_];
__device__ int   g_curi[NI_];
__device__ int   g_bsumu[128];
__device__ int   g_bsumi[128];
__device__ int   g_eidx_ui[NE_];   // src user idx, grouped by dst item
__device__ int   g_eidx_iu[NE_];   // src item idx, grouped by dst user
__device__ float g_wt[131072];     // transposed weights

// ---------------- small helpers ----------------
__device__ __forceinline__ uint32_t smem_u32(const void* p) {
    uint32_t a;
    asm("{ .reg .u64 t; cvta.to.shared.u64 t, %1; cvt.u32.u64 %0, t; }" : "=r"(a) : "l"(p));
    return a;
}

// ---------------- CSR build ----------------
__global__ void zero_cnt_kernel() {
    int i = blockIdx.x * blockDim.x + threadIdx.x;
    if (i < NU_) { g_cntu[i] = 0; g_cnti[i] = 0; }
}

__global__ void count_kernel(const int* __restrict__ eui, const int* __restrict__ eiu) {
    int e = blockIdx.x * blockDim.x + threadIdx.x;
    if (e < NE_) {
        atomicAdd(&g_cnti[eui[NE_ + e]], 1);
        atomicAdd(&g_cntu[eiu[NE_ + e]], 1);
    }
}

// block-level inclusive scan -> exclusive offsets + block totals (y=2 selects u/i)
__global__ void scan1_kernel(int n) {
    const int* cnt = blockIdx.y ? g_cnti : g_cntu;
    int* off  = blockIdx.y ? g_offi  : g_offu;
    int* bsum = blockIdx.y ? g_bsumi : g_bsumu;
    __shared__ int s[1024];
    int t = threadIdx.x, i = blockIdx.x * 1024 + t;
    int v = (i < n) ? cnt[i] : 0;
    s[t] = v;
    __syncthreads();
#pragma unroll
    for (int d = 1; d < 1024; d <<= 1) {
        int y = (t >= d) ? s[t - d] : 0;
        __syncthreads();
        s[t] += y;
        __syncthreads();
    }
    if (i < n) off[i] = s[t] - v;
    if (t == 1023) bsum[blockIdx.x] = s[t];
}

__global__ void scan2_kernel(int nb) {
    int* bsum = blockIdx.x ? g_bsumi : g_bsumu;
    __shared__ int s[128];
    int t = threadIdx.x;
    int v = (t < nb) ? bsum[t] : 0;
    s[t] = v;
    __syncthreads();
#pragma unroll
    for (int d = 1; d < 128; d <<= 1) {
        int y = (t >= d) ? s[t - d] : 0;
        __syncthreads();
        s[t] += y;
        __syncthreads();
    }
    if (t < nb) bsum[t] = s[t] - v;
}

__global__ void scan3_kernel(int n) {
    int* off = blockIdx.y ? g_offi : g_offu;
    const int* bsum = blockIdx.y ? g_bsumi : g_bsumu;
    int* cur = blockIdx.y ? g_curi : g_curu;
    int i = blockIdx.x * 1024 + threadIdx.x;
    if (i < n) {
        int o = off[i] + bsum[blockIdx.x];
        off[i] = o;
        cur[i] = o;
    }
}

__global__ void fill_kernel(const int* __restrict__ eui, const int* __restrict__ eiu) {
    int e = blockIdx.x * blockDim.x + threadIdx.x;
    if (e < NE_) {
        int di = eui[NE_ + e];
        int p  = atomicAdd(&g_curi[di], 1);
        g_eidx_ui[p] = eui[e];
        int du = eiu[NE_ + e];
        int p2 = atomicAdd(&g_curu[du], 1);
        g_eidx_iu[p2] = eiu[e];
    }
}

// ---------------- all weight transposes in one kernel ----------------
// regions in g_wt: [0) pu 128x96 | [12288) pi 128x160 | [32768) ui0 128x256 |
//                  [65536) iu0 128x256 | [98304) iu1 64x256 | [114688) ui1 64x256
__global__ void transpose_all_kernel(
    const float* __restrict__ Wp_u, const float* __restrict__ Wp_i,
    const float* __restrict__ Wl0_ui, const float* __restrict__ Wr0_ui,
    const float* __restrict__ Wl0_iu, const float* __restrict__ Wr0_iu,
    const float* __restrict__ Wl1_iu, const float* __restrict__ Wr1_iu,
    const float* __restrict__ Wl1_ui, const float* __restrict__ Wr1_ui,
    float* __restrict__ dst) {
    int idx = blockIdx.x * blockDim.x + threadIdx.x;
    if (idx >= 131072) return;
    const float *W1, *W2; int K1, KTOT, NOUT, li;
    if (idx < 12288)       { li = idx;          W1 = Wp_u;   W2 = Wp_u;   K1 = 96;  KTOT = 96;  NOUT = 128; }
    else if (idx < 32768)  { li = idx - 12288;  W1 = Wp_i;   W2 = Wp_i;   K1 = 160; KTOT = 160; NOUT = 128; }
    else if (idx < 65536)  { li = idx - 32768;  W1 = Wl0_ui; W2 = Wr0_ui; K1 = 128; KTOT = 256; NOUT = 128; }
    else if (idx < 98304)  { li = idx - 65536;  W1 = Wl0_iu; W2 = Wr0_iu; K1 = 128; KTOT = 256; NOUT = 128; }
    else if (idx < 114688) { li = idx - 98304;  W1 = Wl1_iu; W2 = Wr1_iu; K1 = 128; KTOT = 256; NOUT = 64;  }
    else                   { li = idx - 114688; W1 = Wl1_ui; W2 = Wr1_ui; K1 = 128; KTOT = 256; NOUT = 64;  }
    int n = li / KTOT, k = li % KTOT;
    dst[idx] = (k < K1) ? W1[(size_t)k * NOUT + n] : W2[(size_t)(k - K1) * NOUT + n];
}

// ---------------- projection GEMM (tf32 mma, cp.async + ldmatrix) ----------------
template <int KTOT, int NOUT>
__global__ void __launch_bounds__(256) proj_mma_kernel(
    const float* __restrict__ A1, const float* __restrict__ Wt,
    const float* __restrict__ bias, float* __restrict__ y, int nrows)
{
    constexpr int NT = NOUT / 8;
    constexpr int NC = KTOT / 32;
    constexpr int ABUF = 128 * 32 * 4;
    constexpr int BBUF = NOUT * 32 * 4;
    extern __shared__ __align__(128) char smem[];
    float* s_bias = (float*)(smem + 2 * ABUF + 2 * BBUF);
    uint32_t sb = smem_u32(smem);

    int tid = threadIdx.x;
    int w = tid >> 5, lane = tid & 31;
    int g = lane >> 2, tig = lane & 3;
    int base = blockIdx.x * 128;

    if (tid < NOUT) s_bias[tid] = bias[tid];

    float acc[NT][4];
#pragma unroll
    for (int nt = 0; nt < NT; nt++)
#pragma unroll
        for (int q = 0; q < 4; q++) acc[nt][q] = 0.f;

    auto stage = [&](int c) {
        uint32_t aB = sb + (c & 1) * ABUF;
        uint32_t bB = sb + 2 * ABUF + (c & 1) * BBUF;
        int k0 = c * 32;
#pragma unroll
        for (int t = 0; t < 4; t++) {
            int slot = tid + t * 256;
            int r = slot >> 3, j = slot & 7;
            int gr = base + r;
            const float* src = A1 + (size_t)gr * KTOT + k0 + j * 4;
            uint32_t dst = aB + r * 128 + ((j ^ (r & 7)) << 4);
            int sz = (gr < nrows) ? 16 : 0;
            asm volatile("cp.async.cg.shared.global [%0], [%1], 16, %2;"
                         :: "r"(dst), "l"(src), "r"(sz));
        }
#pragma unroll
        for (int t = 0; t < NOUT / 32; t++) {
            int slot = tid + t * 256;
            int n = slot >> 3, j = slot & 7;
            const float* src = Wt + (size_t)n * KTOT + k0 + j * 4;
            uint32_t dst = bB + n * 128 + ((j ^ (n & 7)) << 4);
            asm volatile("cp.async.cg.shared.global [%0], [%1], 16;"
                         :: "r"(dst), "l"(src));
        }
        asm volatile("cp.async.commit_group;" ::: "memory");
    };

    stage(0);
    for (int c = 0; c < NC; c++) {
        if (c + 1 < NC) {
            stage(c + 1);
            asm volatile("cp.async.wait_group 1;" ::: "memory");
        } else {
            asm volatile("cp.async.wait_group 0;" ::: "memory");
        }
        __syncthreads();
        uint32_t aB = sb + (c & 1) * ABUF;
        uint32_t bB = sb + 2 * ABUF + (c & 1) * BBUF;
#pragma unroll
        for (int kk = 0; kk < 4; kk++) {
            uint32_t a0, a1, a2, a3;
            {
                int m = lane >> 3, i = lane & 7;
                int row = w * 16 + (m & 1) * 8 + i;
                int j = kk * 2 + (m >> 1);
                uint32_t addr = aB + row * 128 + ((j ^ (row & 7)) << 4);
                asm volatile("ldmatrix.sync.aligned.m8n8.x4.shared.b16 {%0,%1,%2,%3}, [%4];"
                             : "=r"(a0), "=r"(a1), "=r"(a2), "=r"(a3) : "r"(addr));
            }
#pragma unroll
            for (int p = 0; p < NT / 2; p++) {
                uint32_t b0, b1, b2, b3;
                {
                    int m = lane >> 3, i = lane & 7;
                    int nrow = p * 16 + (m >> 1) * 8 + i;
                    int j = kk * 2 + (m & 1);
                    uint32_t addr = bB + nrow * 128 + ((j ^ (nrow & 7)) << 4);
                    asm volatile("ldmatrix.sync.aligned.m8n8.x4.shared.b16 {%0,%1,%2,%3}, [%4];"
                                 : "=r"(b0), "=r"(b1), "=r"(b2), "=r"(b3) : "r"(addr));
                }
                asm volatile(
                    "mma.sync.aligned.m16n8k8.row.col.f32.tf32.tf32.f32 "
                    "{%0,%1,%2,%3}, {%4,%5,%6,%7}, {%8,%9}, {%0,%1,%2,%3};"
                    : "+f"(acc[2 * p][0]), "+f"(acc[2 * p][1]), "+f"(acc[2 * p][2]), "+f"(acc[2 * p][3])
                    : "r"(a0), "r"(a1), "r"(a2), "r"(a3), "r"(b0), "r"(b1));
                asm volatile(
                    "mma.sync.aligned.m16n8k8.row.col.f32.tf32.tf32.f32 "
                    "{%0,%1,%2,%3}, {%4,%5,%6,%7}, {%8,%9}, {%0,%1,%2,%3};"
                    : "+f"(acc[2 * p + 1][0]), "+f"(acc[2 * p + 1][1]), "+f"(acc[2 * p + 1][2]), "+f"(acc[2 * p + 1][3])
                    : "r"(a0), "r"(a1), "r"(a2), "r"(a3), "r"(b2), "r"(b3));
            }
        }
        __syncthreads();
    }

    int r0 = base + w * 16 + g;
    int r1 = r0 + 8;
    if (r0 < nrows) {
        float* yr = y + (size_t)r0 * NOUT;
#pragma unroll
        for (int nt = 0; nt < NT; nt++) {
            int cb = nt * 8 + tig * 2;
            float o0 = fmaxf(acc[nt][0] + s_bias[cb], 0.f);
            float o1 = fmaxf(acc[nt][1] + s_bias[cb + 1], 0.f);
            *(float2*)(yr + cb) = make_float2(o0, o1);
        }
    }
    if (r1 < nrows) {
        float* yr = y + (size_t)r1 * NOUT;
#pragma unroll
        for (int nt = 0; nt < NT; nt++) {
            int cb = nt * 8 + tig * 2;
            float o0 = fmaxf(acc[nt][2] + s_bias[cb], 0.f);
            float o1 = fmaxf(acc[nt][3] + s_bias[cb + 1], 0.f);
            *(float2*)(yr + cb) = make_float2(o0, o1);
        }
    }
}

// ---------------- fused gather + SAGE GEMM + LN (+ReLU) ----------------
// blockIdx.y selects side. K = 256: chunks 0-3 = gathered mean agg (computed in
// prologue into swizzled smem slots), chunks 4-7 = root features via cp.async
// reusing slot c-4 after its consumption.
struct SageArgs {
    const float* src0; const float* root0; const int* eidx0; const int* off0; const int* cnt0;
    const float* wt0; const float* bias0; const float* gam0; const float* bet0; float* y0;
    const float* src1; const float* root1; const int* eidx1; const int* off1; const int* cnt1;
    const float* wt1; const float* bias1; const float* gam1; const float* bet1; float* y1;
};

template <int NOUT, bool RELU>
__global__ void __launch_bounds__(256, 2) sage_fused_kernel(SageArgs a, int nrows)
{
    constexpr int NT = NOUT / 8;
    constexpr int ASLOT = 128 * 32 * 4;   // 16KB per K-chunk slot
    constexpr int BBUF = NOUT * 32 * 4;
    extern __shared__ __align__(128) char smem[];
    float* s_bias = (float*)(smem + 4 * ASLOT + 2 * BBUF);
    float* s_g    = s_bias + NOUT;
    float* s_be   = s_g + NOUT;
    uint32_t sb = smem_u32(smem);

    int side = blockIdx.y;
    const float* src  = side ? a.src1  : a.src0;
    const float* root = side ? a.root1 : a.root0;
    const int* eidx   = side ? a.eidx1 : a.eidx0;
    const int* off    = side ? a.off1  : a.off0;
    const int* cnt    = side ? a.cnt1  : a.cnt0;
    const float* Wt   = side ? a.wt1   : a.wt0;
    const float* bias = side ? a.bias1 : a.bias0;
    const float* gam  = side ? a.gam1  : a.gam0;
    const float* bet  = side ? a.bet1  : a.bet0;
    float* y          = side ? a.y1    : a.y0;

    int tid = threadIdx.x;
    int w = tid >> 5, lane = tid & 31;
    int g = lane >> 2, tig = lane & 3;
    int base = blockIdx.x * 128;

    if (tid < NOUT) { s_bias[tid] = bias[tid]; s_g[tid] = gam[tid]; s_be[tid] = bet[tid]; }

    // ---- prologue: gather-mean tile into A slots 0..3 (swizzled) ----
#pragma unroll 1
    for (int rr = 0; rr < 16; rr++) {
        int r = w * 16 + rr;
        int gr = base + r;
        float4 acc4 = make_float4(0.f, 0.f, 0.f, 0.f);
        int c = 0, st = 0;
        if (gr < nrows) { st = off[gr]; c = cnt[gr]; }
        int j = 0;
        for (; j + 2 <= c; j += 2) {
            int s0 = __ldg(&eidx[st + j]);
            int s1 = __ldg(&eidx[st + j + 1]);
            float4 v0 = *(const float4*)(src + (size_t)s0 * HH + lane * 4);
            float4 v1 = *(const float4*)(src + (size_t)s1 * HH + lane * 4);
            acc4.x += v0.x + v1.x; acc4.y += v0.y + v1.y;
            acc4.z += v0.z + v1.z; acc4.w += v0.w + v1.w;
        }
        if (j < c) {
            int s0 = __ldg(&eidx[st + j]);
            float4 v0 = *(const float4*)(src + (size_t)s0 * HH + lane * 4);
            acc4.x += v0.x; acc4.y += v0.y; acc4.z += v0.z; acc4.w += v0.w;
        }
        float sc = 1.f / (float)max(c, 1);
        acc4.x *= sc; acc4.y *= sc; acc4.z *= sc; acc4.w *= sc;
        int cc = lane >> 3, jj = lane & 7;
        *(float4*)(smem + cc * ASLOT + r * 128 + ((jj ^ (r & 7)) << 4)) = acc4;
    }

    float acc[NT][4];
#pragma unroll
    for (int nt = 0; nt < NT; nt++)
#pragma unroll
        for (int q = 0; q < 4; q++) acc[nt][q] = 0.f;

    auto stageB = [&](int c) {
        uint32_t bB = sb + 4 * ASLOT + (c & 1) * BBUF;
#pragma unroll
        for (int t = 0; t < NOUT / 32; t++) {
            int slot = tid + t * 256;
            int n = slot >> 3, j = slot & 7;
            const float* s = Wt + (size_t)n * 256 + c * 32 + j * 4;
            uint32_t dst = bB + n * 128 + ((j ^ (n & 7)) << 4);
            asm volatile("cp.async.cg.shared.global [%0], [%1], 16;"
                         :: "r"(dst), "l"(s));
        }
    };
    auto stageA = [&](int c) {   // c in 4..7 -> slot c-4, source = root chunk c-4
        uint32_t aB = sb + (c - 4) * ASLOT;
#pragma unroll
        for (int t = 0; t < 4; t++) {
            int slot = tid + t * 256;
            int r = slot >> 3, j = slot & 7;
            int gr = base + r;
            const float* s = root + (size_t)gr * HH + (c - 4) * 32 + j * 4;
            uint32_t dst = aB + r * 128 + ((j ^ (r & 7)) << 4);
            int sz = (gr < nrows) ? 16 : 0;
            asm volatile("cp.async.cg.shared.global [%0], [%1], 16, %2;"
                         :: "r"(dst), "l"(s), "r"(sz));
        }
    };

    stageB(0);
    asm volatile("cp.async.commit_group;" ::: "memory");
    __syncthreads();   // gather tile complete for all warps

    for (int c = 0; c < 8; c++) {
        if (c < 7) stageB(c + 1);
        if (c >= 1 && c <= 4) stageA(c + 3);   // fills slot c-1 (freed at end of iter c-1)
        asm volatile("cp.async.commit_group;" ::: "memory");
        if (c < 7) asm volatile("cp.async.wait_group 1;" ::: "memory");
        else       asm volatile("cp.async.wait_group 0;" ::: "memory");
        __syncthreads();

        uint32_t aB = sb + ((c < 4) ? c : c - 4) * ASLOT;
        uint32_t bB = sb + 4 * ASLOT + (c & 1) * BBUF;
#pragma unroll
        for (int kk = 0; kk < 4; kk++) {
            uint32_t a0, a1, a2, a3;
            {
                int m = lane >> 3, i = lane & 7;
                int row = w * 16 + (m & 1) * 8 + i;
                int j = kk * 2 + (m >> 1);
                uint32_t addr = aB + row * 128 + ((j ^ (row & 7)) << 4);
                asm volatile("ldmatrix.sync.aligned.m8n8.x4.shared.b16 {%0,%1,%2,%3}, [%4];"
                             : "=r"(a0), "=r"(a1), "=r"(a2), "=r"(a3) : "r"(addr));
            }
#pragma unroll
            for (int p = 0; p < NT / 2; p++) {
                uint32_t b0, b1, b2, b3;
                {
                    int m = lane >> 3, i = lane & 7;
                    int nrow = p * 16 + (m >> 1) * 8 + i;
                    int j = kk * 2 + (m & 1);
                    uint32_t addr = bB + nrow * 128 + ((j ^ (nrow & 7)) << 4);
                    asm volatile("ldmatrix.sync.aligned.m8n8.x4.shared.b16 {%0,%1,%2,%3}, [%4];"
                                 : "=r"(b0), "=r"(b1), "=r"(b2), "=r"(b3) : "r"(addr));
                }
                asm volatile(
                    "mma.sync.aligned.m16n8k8.row.col.f32.tf32.tf32.f32 "
                    "{%0,%1,%2,%3}, {%4,%5,%6,%7}, {%8,%9}, {%0,%1,%2,%3};"
                    : "+f"(acc[2 * p][0]), "+f"(acc[2 * p][1]), "+f"(acc[2 * p][2]), "+f"(acc[2 * p][3])
                    : "r"(a0), "r"(a1), "r"(a2), "r"(a3), "r"(b0), "r"(b1));
                asm volatile(
                    "mma.sync.aligned.m16n8k8.row.col.f32.tf32.tf32.f32 "
                    "{%0,%1,%2,%3}, {%4,%5,%6,%7}, {%8,%9}, {%0,%1,%2,%3};"
                    : "+f"(acc[2 * p + 1][0]), "+f"(acc[2 * p + 1][1]), "+f"(acc[2 * p + 1][2]), "+f"(acc[2 * p + 1][3])
                    : "r"(a0), "r"(a1), "r"(a2), "r"(a3), "r"(b2), "r"(b3));
            }
        }
        __syncthreads();
    }

    // ---- epilogue: bias + LN (+ReLU) ----
    int r0 = base + w * 16 + g;
    int r1 = r0 + 8;

#pragma unroll
    for (int nt = 0; nt < NT; nt++) {
        int cb = nt * 8 + tig * 2;
        float b0f = s_bias[cb], b1f = s_bias[cb + 1];
        acc[nt][0] += b0f; acc[nt][1] += b1f;
        acc[nt][2] += b0f; acc[nt][3] += b1f;
    }

    float s0 = 0.f, q0 = 0.f, s1 = 0.f, q1 = 0.f;
#pragma unroll
    for (int nt = 0; nt < NT; nt++) {
        s0 += acc[nt][0] + acc[nt][1];
        q0 += acc[nt][0] * acc[nt][0] + acc[nt][1] * acc[nt][1];
        s1 += acc[nt][2] + acc[nt][3];
        q1 += acc[nt][2] * acc[nt][2] + acc[nt][3] * acc[nt][3];
    }
#pragma unroll
    for (int m = 1; m <= 2; m <<= 1) {
        s0 += __shfl_xor_sync(0xffffffffu, s0, m);
        q0 += __shfl_xor_sync(0xffffffffu, q0, m);
        s1 += __shfl_xor_sync(0xffffffffu, s1, m);
        q1 += __shfl_xor_sync(0xffffffffu, q1, m);
    }
    float mean0 = s0 / (float)NOUT;
    float mean1 = s1 / (float)NOUT;
    float rs0 = rsqrtf(q0 / (float)NOUT - mean0 * mean0 + LN_EPS);
    float rs1 = rsqrtf(q1 / (float)NOUT - mean1 * mean1 + LN_EPS);

    if (r0 < nrows) {
        float* yr = y + (size_t)r0 * NOUT;
#pragma unroll
        for (int nt = 0; nt < NT; nt++) {
            int cb = nt * 8 + tig * 2;
            float o0 = (acc[nt][0] - mean0) * rs0 * s_g[cb]     + s_be[cb];
            float o1 = (acc[nt][1] - mean0) * rs0 * s_g[cb + 1] + s_be[cb + 1];
            if (RELU) { o0 = fmaxf(o0, 0.f); o1 = fmaxf(o1, 0.f); }
            *(float2*)(yr + cb) = make_float2(o0, o1);
        }
    }
    if (r1 < nrows) {
        float* yr = y + (size_t)r1 * NOUT;
#pragma unroll
        for (int nt = 0; nt < NT; nt++) {
            int cb = nt * 8 + tig * 2;
            float o0 = (acc[nt][2] - mean1) * rs1 * s_g[cb]     + s_be[cb];
            float o1 = (acc[nt][3] - mean1) * rs1 * s_g[cb + 1] + s_be[cb + 1];
            if (RELU) { o0 = fmaxf(o0, 0.f); o1 = fmaxf(o1, 0.f); }
            *(float2*)(yr + cb) = make_float2(o0, o1);
        }
    }
}

// ---------------- launcher ----------------
extern "C" void kernel_launch(void* const* d_in, const int* in_sizes, int n_in,
                              void* d_out, int out_size) {
    (void)in_sizes; (void)n_in; (void)out_size;
    const float* x_user = (const float*)d_in[0];
    const float* x_item = (const float*)d_in[1];
    const int*   eui    = (const int*)d_in[2];
    const int*   eiu    = (const int*)d_in[3];
    const float* Wp_u   = (const float*)d_in[4];
    const float* bp_u   = (const float*)d_in[5];
    const float* Wp_i   = (const float*)d_in[6];
    const float* bp_i   = (const float*)d_in[7];
    const float* Wl0_ui = (const float*)d_in[8];
    const float* bl0_ui = (const float*)d_in[9];
    const float* Wr0_ui = (const float*)d_in[10];
    const float* Wl0_iu = (const float*)d_in[11];
    const float* bl0_iu = (const float*)d_in[12];
    const float* Wr0_iu = (const float*)d_in[13];
    const float* g0_u   = (const float*)d_in[14];
    const float* b0_u   = (const float*)d_in[15];
    const float* g0_i   = (const float*)d_in[16];
    const float* b0_i   = (const float*)d_in[17];
    const float* Wl1_ui = (const float*)d_in[18];
    const float* bl1_ui = (const float*)d_in[19];
    const float* Wr1_ui = (const float*)d_in[20];
    const float* Wl1_iu = (const float*)d_in[21];
    const float* bl1_iu = (const float*)d_in[22];
    const float* Wr1_iu = (const float*)d_in[23];
    const float* g1_u   = (const float*)d_in[24];
    const float* b1_u   = (const float*)d_in[25];
    const float* g1_i   = (const float*)d_in[26];
    const float* b1_i   = (const float*)d_in[27];

    float *hu, *hi, *hu1, *hi1, *wt;
    int *cntu, *cnti, *offu, *offi, *eix_ui, *eix_iu;
    cudaGetSymbolAddress((void**)&hu,   g_hu);
    cudaGetSymbolAddress((void**)&hi,   g_hi);
    cudaGetSymbolAddress((void**)&hu1,  g_hu1);
    cudaGetSymbolAddress((void**)&hi1,  g_hi1);
    cudaGetSymbolAddress((void**)&wt,   g_wt);
    cudaGetSymbolAddress((void**)&cntu, g_cntu);
    cudaGetSymbolAddress((void**)&cnti, g_cnti);
    cudaGetSymbolAddress((void**)&offu, g_offu);
    cudaGetSymbolAddress((void**)&offi, g_offi);
    cudaGetSymbolAddress((void**)&eix_ui, g_eidx_ui);
    cudaGetSymbolAddress((void**)&eix_iu, g_eidx_iu);

    float* out = (float*)d_out;

    float* wt_pu  = wt;             // 128 x 96
    float* wt_pi  = wt + 12288;     // 128 x 160
    float* wt0_ui = wt + 32768;     // 128 x 256
    float* wt0_iu = wt + 65536;     // 128 x 256
    float* wt1_iu = wt + 98304;     // 64 x 256
    float* wt1_ui = wt + 114688;    // 64 x 256

    const int SM_P96  = 2 * (128 * 32 * 4) + 2 * (128 * 32 * 4) + 128 * 4;      // 66048
    const int SM_P160 = SM_P96;
    const int SM_S128 = 4 * (128 * 32 * 4) + 2 * (128 * 32 * 4) + 3 * 128 * 4;  // 99840
    const int SM_S64  = 4 * (128 * 32 * 4) + 2 * (64 * 32 * 4)  + 3 * 64 * 4;   // 82688
    cudaFuncSetAttribute(proj_mma_kernel<FU_, HH>,
                         cudaFuncAttributeMaxDynamicSharedMemorySize, SM_P96);
    cudaFuncSetAttribute(proj_mma_kernel<FI_, HH>,
                         cudaFuncAttributeMaxDynamicSharedMemorySize, SM_P160);
    cudaFuncSetAttribute(sage_fused_kernel<HH, true>,
                         cudaFuncAttributeMaxDynamicSharedMemorySize, SM_S128);
    cudaFuncSetAttribute(sage_fused_kernel<OUTD, false>,
                         cudaFuncAttributeMaxDynamicSharedMemorySize, SM_S64);

    const int gblocks = (NU_ + 127) / 128;     // 782
    const int sblocks = (NU_ + 1023) / 1024;   // 98

    // CSR build (shared by both layers)
    zero_cnt_kernel<<<(NU_ + 255) / 256, 256>>>();
    count_kernel<<<(NE_ + 255) / 256, 256>>>(eui, eiu);
    scan1_kernel<<<dim3(sblocks, 2), 1024>>>(NU_);
    scan2_kernel<<<2, 128>>>(sblocks);
    scan3_kernel<<<dim3(sblocks, 2), 1024>>>(NU_);
    fill_kernel<<<(NE_ + 255) / 256, 256>>>(eui, eiu);

    // all weight transposes
    transpose_all_kernel<<<(131072 + 255) / 256, 256>>>(
        Wp_u, Wp_i, Wl0_ui, Wr0_ui, Wl0_iu, Wr0_iu, Wl1_iu, Wr1_iu, Wl1_ui, Wr1_ui, wt);

    // projections + relu
    proj_mma_kernel<FU_, HH><<<gblocks, 256, SM_P96>>>(x_user, wt_pu, bp_u, hu, NU_);
    proj_mma_kernel<FI_, HH><<<gblocks, 256, SM_P160>>>(x_item, wt_pi, bp_i, hi, NI_);

    // layer 0: fused gather + SAGE + LN + relu (side 0 = items, side 1 = users)
    SageArgs a0;
    a0.src0 = hu;  a0.root0 = hi;  a0.eidx0 = eix_ui; a0.off0 = offi; a0.cnt0 = cnti;
    a0.wt0 = wt0_ui; a0.bias0 = bl0_ui; a0.gam0 = g0_i; a0.bet0 = b0_i; a0.y0 = hi1;
    a0.src1 = hi;  a0.root1 = hu;  a0.eidx1 = eix_iu; a0.off1 = offu; a0.cnt1 = cntu;
    a0.wt1 = wt0_iu; a0.bias1 = bl0_iu; a0.gam1 = g0_u; a0.bet1 = b0_u; a0.y1 = hu1;
    sage_fused_kernel<HH, true><<<dim3(gblocks, 2), 256, SM_S128>>>(a0, NU_);

    // layer 1: fused gather + SAGE + LN (no relu); outputs [h_u2 | h_i2]
    SageArgs a1;
    a1.src0 = hu1; a1.root0 = hi1; a1.eidx0 = eix_ui; a1.off0 = offi; a1.cnt0 = cnti;
    a1.wt0 = wt1_ui; a1.bias0 = bl1_ui; a1.gam0 = g1_i; a1.bet0 = b1_i;
    a1.y0 = out + (size_t)NU_ * OUTD;
    a1.src1 = hi1; a1.root1 = hu1; a1.eidx1 = eix_iu; a1.off1 = offu; a1.cnt1 = cntu;
    a1.wt1 = wt1_iu; a1.bias1 = bl1_iu; a1.gam1 = g1_u; a1.bet1 = b1_u;
    a1.y1 = out;
    sage_fused_kernel<OUTD, false><<<dim3(gblocks, 2), 256, SM_S64>>>(a1, NU_);
}

// round 13
// speedup vs baseline: 1.1148x; 1.1148x over previous
#include <cuda_runtime.h>
#include <cstdint>

#define NU_  100000
#define NI_  100000
#define NE_  600000
#define FU_  96
#define FI_  160
#define HH   128
#define OUTD 64
#define LN_EPS 1e-5f

// ---------------- scratch (device globals; no runtime allocation) ----------------
__device__ float g_hu  [NU_ * HH];
__device__ float g_hi  [NI_ * HH];
__device__ float g_aggu[NU_ * HH];
__device__ float g_aggi[NI_ * HH];
__device__ float g_hu1 [NU_ * HH];
__device__ float g_hi1 [NI_ * HH];
__device__ int   g_cntu[NU_];
__device__ int   g_cnti[NI_];
__device__ int   g_offu[NU_];
__device__ int   g_offi[NI_];
__device__ int   g_curu[NU_];
__device__ int   g_curi[NI_];
__device__ int   g_bsumu[128];
__device__ int   g_bsumi[128];
__device__ int   g_eidx_ui[NE_];   // src user idx, grouped by dst item
__device__ int   g_eidx_iu[NE_];   // src item idx, grouped by dst user
__device__ float g_wt[131072];     // transposed weights

// ---------------- small helpers ----------------
__device__ __forceinline__ uint32_t smem_u32(const void* p) {
    uint32_t a;
    asm("{ .reg .u64 t; cvta.to.shared.u64 t, %1; cvt.u32.u64 %0, t; }" : "=r"(a) : "l"(p));
    return a;
}

// ---------------- CSR build ----------------
__global__ void count_kernel(const int* __restrict__ eui, const int* __restrict__ eiu) {
    int e = blockIdx.x * blockDim.x + threadIdx.x;
    if (e < NE_) {
        atomicAdd(&g_cnti[eui[NE_ + e]], 1);
        atomicAdd(&g_cntu[eiu[NE_ + e]], 1);
    }
}

// block-level inclusive scan -> exclusive offsets + block totals (y selects u/i)
__global__ void scan1_kernel(int n) {
    const int* cnt = blockIdx.y ? g_cnti : g_cntu;
    int* off  = blockIdx.y ? g_offi  : g_offu;
    int* bsum = blockIdx.y ? g_bsumi : g_bsumu;
    __shared__ int s[1024];
    int t = threadIdx.x, i = blockIdx.x * 1024 + t;
    int v = (i < n) ? cnt[i] : 0;
    s[t] = v;
    __syncthreads();
#pragma unroll
    for (int d = 1; d < 1024; d <<= 1) {
        int y = (t >= d) ? s[t - d] : 0;
        __syncthreads();
        s[t] += y;
        __syncthreads();
    }
    if (i < n) off[i] = s[t] - v;
    if (t == 1023) bsum[blockIdx.x] = s[t];
}

__global__ void scan2_kernel(int nb) {
    int* bsum = blockIdx.x ? g_bsumi : g_bsumu;
    __shared__ int s[128];
    int t = threadIdx.x;
    int v = (t < nb) ? bsum[t] : 0;
    s[t] = v;
    __syncthreads();
#pragma unroll
    for (int d = 1; d < 128; d <<= 1) {
        int y = (t >= d) ? s[t - d] : 0;
        __syncthreads();
        s[t] += y;
        __syncthreads();
    }
    if (t < nb) bsum[t] = s[t] - v;
}

__global__ void scan3_kernel(int n) {
    int* off = blockIdx.y ? g_offi : g_offu;
    const int* bsum = blockIdx.y ? g_bsumi : g_bsumu;
    int* cur = blockIdx.y ? g_curi : g_curu;
    int i = blockIdx.x * 1024 + threadIdx.x;
    if (i < n) {
        int o = off[i] + bsum[blockIdx.x];
        off[i] = o;
        cur[i] = o;
    }
}

__global__ void fill_kernel(const int* __restrict__ eui, const int* __restrict__ eiu) {
    int e = blockIdx.x * blockDim.x + threadIdx.x;
    if (e < NE_) {
        int di = eui[NE_ + e];
        int p  = atomicAdd(&g_curi[di], 1);
        g_eidx_ui[p] = eui[e];
        int du = eiu[NE_ + e];
        int p2 = atomicAdd(&g_curu[du], 1);
        g_eidx_iu[p2] = eiu[e];
    }
}

// ---------------- dual gather-mean aggregation: warp per destination row ----------------
struct GatherArgs {
    const float* feat0; const int* eidx0; const int* off0; const int* cnt0; float* agg0;
    const float* feat1; const int* eidx1; const int* off1; const int* cnt1; float* agg1;
};

__global__ void gather_kernel(GatherArgs a, int n) {
    const float* feat = blockIdx.y ? a.feat1 : a.feat0;
    const int* eidx   = blockIdx.y ? a.eidx1 : a.eidx0;
    const int* off    = blockIdx.y ? a.off1  : a.off0;
    const int* cnt    = blockIdx.y ? a.cnt1  : a.cnt0;
    float* agg        = blockIdx.y ? a.agg1  : a.agg0;
    int gw = (int)(((long long)blockIdx.x * blockDim.x + threadIdx.x) >> 5);
    if (gw >= n) return;
    int lane = threadIdx.x & 31;
    int start = off[gw], c = cnt[gw];
    float4 a0 = make_float4(0.f, 0.f, 0.f, 0.f);
    float4 a1 = make_float4(0.f, 0.f, 0.f, 0.f);
    int j = 0;
    for (; j + 2 <= c; j += 2) {
        int s0 = __ldg(&eidx[start + j]);
        int s1 = __ldg(&eidx[start + j + 1]);
        float4 v0 = *(const float4*)(feat + (size_t)s0 * HH + lane * 4);
        float4 v1 = *(const float4*)(feat + (size_t)s1 * HH + lane * 4);
        a0.x += v0.x; a0.y += v0.y; a0.z += v0.z; a0.w += v0.w;
        a1.x += v1.x; a1.y += v1.y; a1.z += v1.z; a1.w += v1.w;
    }
    if (j < c) {
        int s0 = __ldg(&eidx[start + j]);
        float4 v0 = *(const float4*)(feat + (size_t)s0 * HH + lane * 4);
        a0.x += v0.x; a0.y += v0.y; a0.z += v0.z; a0.w += v0.w;
    }
    float sc = 1.f / (float)max(c, 1);
    float4 r = make_float4((a0.x + a1.x) * sc, (a0.y + a1.y) * sc,
                           (a0.z + a1.z) * sc, (a0.w + a1.w) * sc);
    *(float4*)(agg + (size_t)gw * HH + lane * 4) = r;
}

// ---------------- weight transposes (+ zero the CSR counters) ----------------
// regions in g_wt: [0) pu 128x96 | [12288) pi 128x160 | [32768) ui0 128x256 |
//                  [65536) iu0 128x256 | [98304) iu1 64x256 | [114688) ui1 64x256
__global__ void transpose_all_kernel(
    const float* __restrict__ Wp_u, const float* __restrict__ Wp_i,
    const float* __restrict__ Wl0_ui, const float* __restrict__ Wr0_ui,
    const float* __restrict__ Wl0_iu, const float* __restrict__ Wr0_iu,
    const float* __restrict__ Wl1_iu, const float* __restrict__ Wr1_iu,
    const float* __restrict__ Wl1_ui, const float* __restrict__ Wr1_ui,
    float* __restrict__ dst) {
    int idx = blockIdx.x * blockDim.x + threadIdx.x;
    if (idx < NU_) { g_cntu[idx] = 0; g_cnti[idx] = 0; }
    if (idx >= 131072) return;
    const float *W1, *W2; int K1, KTOT, NOUT, li;
    if (idx < 12288)       { li = idx;          W1 = Wp_u;   W2 = Wp_u;   K1 = 96;  KTOT = 96;  NOUT = 128; }
    else if (idx < 32768)  { li = idx - 12288;  W1 = Wp_i;   W2 = Wp_i;   K1 = 160; KTOT = 160; NOUT = 128; }
    else if (idx < 65536)  { li = idx - 32768;  W1 = Wl0_ui; W2 = Wr0_ui; K1 = 128; KTOT = 256; NOUT = 128; }
    else if (idx < 98304)  { li = idx - 65536;  W1 = Wl0_iu; W2 = Wr0_iu; K1 = 128; KTOT = 256; NOUT = 128; }
    else if (idx < 114688) { li = idx - 98304;  W1 = Wl1_iu; W2 = Wr1_iu; K1 = 128; KTOT = 256; NOUT = 64;  }
    else                   { li = idx - 114688; W1 = Wl1_ui; W2 = Wr1_ui; K1 = 128; KTOT = 256; NOUT = 64;  }
    int n = li / KTOT, k = li % KTOT;
    dst[idx] = (k < K1) ? W1[(size_t)k * NOUT + n] : W2[(size_t)(k - K1) * NOUT + n];
}

// ======================= tf32 mma GEMM core (3-stage cp.async) =======================
// block: 256 thr = 8 warps, 128 rows; warp: m16 x NOUT; K in chunks of 32, 3 buffers,
// ONE __syncthreads per chunk.

template <int NOUT>
struct MmaCore {
    static constexpr int NT = NOUT / 8;
    static constexpr int ABUF = 128 * 32 * 4;
    static constexpr int BBUF = NOUT * 32 * 4;

    uint32_t sb; int tid, w, lane;

    __device__ __forceinline__ void stageA_row(const float* src, int rowlen, int ak,
                                               int c, int base, int nrows) {
        uint32_t aB = sb + (c % 3) * ABUF;
#pragma unroll
        for (int t = 0; t < 4; t++) {
            int slot = tid + t * 256;
            int r = slot >> 3, j = slot & 7;
            int gr = base + r;
            const float* s = src + (size_t)gr * rowlen + ak + j * 4;
            uint32_t dst = aB + r * 128 + ((j ^ (r & 7)) << 4);
            int sz = (gr < nrows) ? 16 : 0;
            asm volatile("cp.async.cg.shared.global [%0], [%1], 16, %2;"
                         :: "r"(dst), "l"(s), "r"(sz));
        }
    }
    __device__ __forceinline__ void stageB(const float* Wt, int ktot, int c) {
        uint32_t bB = sb + 3 * ABUF + (c % 3) * BBUF;
#pragma unroll
        for (int t = 0; t < NOUT / 32; t++) {
            int slot = tid + t * 256;
            int n = slot >> 3, j = slot & 7;
            const float* s = Wt + (size_t)n * ktot + c * 32 + j * 4;
            uint32_t dst = bB + n * 128 + ((j ^ (n & 7)) << 4);
            asm volatile("cp.async.cg.shared.global [%0], [%1], 16;"
                         :: "r"(dst), "l"(s));
        }
    }
    __device__ __forceinline__ void compute(int c, float (*acc)[4]) {
        uint32_t aB = sb + (c % 3) * ABUF;
        uint32_t bB = sb + 3 * ABUF + (c % 3) * BBUF;
#pragma unroll
        for (int kk = 0; kk < 4; kk++) {
            uint32_t a0, a1, a2, a3;
            {
                int m = lane >> 3, i = lane & 7;
                int row = w * 16 + (m & 1) * 8 + i;
                int j = kk * 2 + (m >> 1);
                uint32_t addr = aB + row * 128 + ((j ^ (row & 7)) << 4);
                asm volatile("ldmatrix.sync.aligned.m8n8.x4.shared.b16 {%0,%1,%2,%3}, [%4];"
                             : "=r"(a0), "=r"(a1), "=r"(a2), "=r"(a3) : "r"(addr));
            }
#pragma unroll
            for (int p = 0; p < NT / 2; p++) {
                uint32_t b0, b1, b2, b3;
                {
                    int m = lane >> 3, i = lane & 7;
                    int nrow = p * 16 + (m >> 1) * 8 + i;
                    int j = kk * 2 + (m & 1);
                    uint32_t addr = bB + nrow * 128 + ((j ^ (nrow & 7)) << 4);
                    asm volatile("ldmatrix.sync.aligned.m8n8.x4.shared.b16 {%0,%1,%2,%3}, [%4];"
                                 : "=r"(b0), "=r"(b1), "=r"(b2), "=r"(b3) : "r"(addr));
                }
                asm volatile(
                    "mma.sync.aligned.m16n8k8.row.col.f32.tf32.tf32.f32 "
                    "{%0,%1,%2,%3}, {%4,%5,%6,%7}, {%8,%9}, {%0,%1,%2,%3};"
                    : "+f"(acc[2 * p][0]), "+f"(acc[2 * p][1]), "+f"(acc[2 * p][2]), "+f"(acc[2 * p][3])
                    : "r"(a0), "r"(a1), "r"(a2), "r"(a3), "r"(b0), "r"(b1));
                asm volatile(
                    "mma.sync.aligned.m16n8k8.row.col.f32.tf32.tf32.f32 "
                    "{%0,%1,%2,%3}, {%4,%5,%6,%7}, {%8,%9}, {%0,%1,%2,%3};"
                    : "+f"(acc[2 * p + 1][0]), "+f"(acc[2 * p + 1][1]), "+f"(acc[2 * p + 1][2]), "+f"(acc[2 * p + 1][3])
                    : "r"(a0), "r"(a1), "r"(a2), "r"(a3), "r"(b2), "r"(b3));
            }
        }
    }
};

// ---------------- projection GEMM: y = relu(X @ Wp + b) ----------------
template <int KTOT, int NOUT>
__global__ void __launch_bounds__(256) proj_mma_kernel(
    const float* __restrict__ A, const float* __restrict__ Wt,
    const float* __restrict__ bias, float* __restrict__ y, int nrows)
{
    constexpr int NT = NOUT / 8;
    constexpr int NC = KTOT / 32;
    using Core = MmaCore<NOUT>;
    extern __shared__ __align__(128) char smem[];
    float* s_bias = (float*)(smem + 3 * Core::ABUF + 3 * Core::BBUF);

    Core core;
    core.sb = smem_u32(smem);
    core.tid = threadIdx.x;
    core.w = threadIdx.x >> 5;
    core.lane = threadIdx.x & 31;
    int g = core.lane >> 2, tig = core.lane & 3;
    int base = blockIdx.x * 128;

    if (core.tid < NOUT) s_bias[core.tid] = bias[core.tid];

    float acc[NT][4];
#pragma unroll
    for (int nt = 0; nt < NT; nt++)
#pragma unroll
        for (int q = 0; q < 4; q++) acc[nt][q] = 0.f;

    auto stage = [&](int c) {
        core.stageA_row(A, KTOT, c * 32, c, base, nrows);
        core.stageB(Wt, KTOT, c);
        asm volatile("cp.async.commit_group;" ::: "memory");
    };

    stage(0);
    if (NC > 1) stage(1);
    for (int c = 0; c < NC; c++) {
        if (c + 1 < NC) asm volatile("cp.async.wait_group 1;" ::: "memory");
        else            asm volatile("cp.async.wait_group 0;" ::: "memory");
        __syncthreads();
        core.compute(c, acc);
        if (c + 2 < NC) stage(c + 2);
    }

    int r0 = base + core.w * 16 + g;
    int r1 = r0 + 8;
    if (r0 < nrows) {
        float* yr = y + (size_t)r0 * NOUT;
#pragma unroll
        for (int nt = 0; nt < NT; nt++) {
            int cb = nt * 8 + tig * 2;
            float o0 = fmaxf(acc[nt][0] + s_bias[cb], 0.f);
            float o1 = fmaxf(acc[nt][1] + s_bias[cb + 1], 0.f);
            *(float2*)(yr + cb) = make_float2(o0, o1);
        }
    }
    if (r1 < nrows) {
        float* yr = y + (size_t)r1 * NOUT;
#pragma unroll
        for (int nt = 0; nt < NT; nt++) {
            int cb = nt * 8 + tig * 2;
            float o0 = fmaxf(acc[nt][2] + s_bias[cb], 0.f);
            float o1 = fmaxf(acc[nt][3] + s_bias[cb + 1], 0.f);
            *(float2*)(yr + cb) = make_float2(o0, o1);
        }
    }
}

// ---------------- dual SAGE GEMM + LN (+ReLU): y = LN([agg|root] @ Wt^T + b) ----------------
struct SageArgs {
    const float* agg0; const float* root0; const float* wt0;
    const float* bias0; const float* gam0; const float* bet0; float* y0;
    const float* agg1; const float* root1; const float* wt1;
    const float* bias1; const float* gam1; const float* bet1; float* y1;
};

template <int NOUT, bool RELU>
__global__ void __launch_bounds__(256) sage_mma_kernel(SageArgs a, int nrows)
{
    constexpr int NT = NOUT / 8;
    constexpr int NC = 8;   // K = 256
    using Core = MmaCore<NOUT>;
    extern __shared__ __align__(128) char smem[];
    float* s_bias = (float*)(smem + 3 * Core::ABUF + 3 * Core::BBUF);
    float* s_g    = s_bias + NOUT;
    float* s_be   = s_g + NOUT;

    int side = blockIdx.y;
    const float* agg  = side ? a.agg1  : a.agg0;
    const float* root = side ? a.root1 : a.root0;
    const float* Wt   = side ? a.wt1   : a.wt0;
    const float* bias = side ? a.bias1 : a.bias0;
    const float* gam  = side ? a.gam1  : a.gam0;
    const float* bet  = side ? a.bet1  : a.bet0;
    float* y          = side ? a.y1    : a.y0;

    Core core;
    core.sb = smem_u32(smem);
    core.tid = threadIdx.x;
    core.w = threadIdx.x >> 5;
    core.lane = threadIdx.x & 31;
    int g = core.lane >> 2, tig = core.lane & 3;
    int base = blockIdx.x * 128;

    if (core.tid < NOUT) {
        s_bias[core.tid] = bias[core.tid];
        s_g[core.tid] = gam[core.tid];
        s_be[core.tid] = bet[core.tid];
    }

    float acc[NT][4];
#pragma unroll
    for (int nt = 0; nt < NT; nt++)
#pragma unroll
        for (int q = 0; q < 4; q++) acc[nt][q] = 0.f;

    auto stage = [&](int c) {
        if (c < 4) core.stageA_row(agg,  HH, c * 32,       c, base, nrows);
        else       core.stageA_row(root, HH, (c - 4) * 32, c, base, nrows);
        core.stageB(Wt, 256, c);
        asm volatile("cp.async.commit_group;" ::: "memory");
    };

    stage(0);
    stage(1);
    for (int c = 0; c < NC; c++) {
        if (c + 1 < NC) asm volatile("cp.async.wait_group 1;" ::: "memory");
        else            asm volatile("cp.async.wait_group 0;" ::: "memory");
        __syncthreads();
        core.compute(c, acc);
        if (c + 2 < NC) stage(c + 2);
    }

    // ---- epilogue: bias + LN (+ReLU) ----
    int r0 = base + core.w * 16 + g;
    int r1 = r0 + 8;

#pragma unroll
    for (int nt = 0; nt < NT; nt++) {
        int cb = nt * 8 + tig * 2;
        float b0f = s_bias[cb], b1f = s_bias[cb + 1];
        acc[nt][0] += b0f; acc[nt][1] += b1f;
        acc[nt][2] += b0f; acc[nt][3] += b1f;
    }

    float s0 = 0.f, q0 = 0.f, s1 = 0.f, q1 = 0.f;
#pragma unroll
    for (int nt = 0; nt < NT; nt++) {
        s0 += acc[nt][0] + acc[nt][1];
        q0 += acc[nt][0] * acc[nt][0] + acc[nt][1] * acc[nt][1];
        s1 += acc[nt][2] + acc[nt][3];
        q1 += acc[nt][2] * acc[nt][2] + acc[nt][3] * acc[nt][3];
    }
#pragma unroll
    for (int m = 1; m <= 2; m <<= 1) {
        s0 += __shfl_xor_sync(0xffffffffu, s0, m);
        q0 += __shfl_xor_sync(0xffffffffu, q0, m);
        s1 += __shfl_xor_sync(0xffffffffu, s1, m);
        q1 += __shfl_xor_sync(0xffffffffu, q1, m);
    }
    float mean0 = s0 / (float)NOUT;
    float mean1 = s1 / (float)NOUT;
    float rs0 = rsqrtf(q0 / (float)NOUT - mean0 * mean0 + LN_EPS);
    float rs1 = rsqrtf(q1 / (float)NOUT - mean1 * mean1 + LN_EPS);

    if (r0 < nrows) {
        float* yr = y + (size_t)r0 * NOUT;
#pragma unroll
        for (int nt = 0; nt < NT; nt++) {
            int cb = nt * 8 + tig * 2;
            float o0 = (acc[nt][0] - mean0) * rs0 * s_g[cb]     + s_be[cb];
            float o1 = (acc[nt][1] - mean0) * rs0 * s_g[cb + 1] + s_be[cb + 1];
            if (RELU) { o0 = fmaxf(o0, 0.f); o1 = fmaxf(o1, 0.f); }
            *(float2*)(yr + cb) = make_float2(o0, o1);
        }
    }
    if (r1 < nrows) {
        float* yr = y + (size_t)r1 * NOUT;
#pragma unroll
        for (int nt = 0; nt < NT; nt++) {
            int cb = nt * 8 + tig * 2;
            float o0 = (acc[nt][2] - mean1) * rs1 * s_g[cb]     + s_be[cb];
            float o1 = (acc[nt][3] - mean1) * rs1 * s_g[cb + 1] + s_be[cb + 1];
            if (RELU) { o0 = fmaxf(o0, 0.f); o1 = fmaxf(o1, 0.f); }
            *(float2*)(yr + cb) = make_float2(o0, o1);
        }
    }
}

// ---------------- launcher ----------------
extern "C" void kernel_launch(void* const* d_in, const int* in_sizes, int n_in,
                              void* d_out, int out_size) {
    (void)in_sizes; (void)n_in; (void)out_size;
    const float* x_user = (const float*)d_in[0];
    const float* x_item = (const float*)d_in[1];
    const int*   eui    = (const int*)d_in[2];
    const int*   eiu    = (const int*)d_in[3];
    const float* Wp_u   = (const float*)d_in[4];
    const float* bp_u   = (const float*)d_in[5];
    const float* Wp_i   = (const float*)d_in[6];
    const float* bp_i   = (const float*)d_in[7];
    const float* Wl0_ui = (const float*)d_in[8];
    const float* bl0_ui = (const float*)d_in[9];
    const float* Wr0_ui = (const float*)d_in[10];
    const float* Wl0_iu = (const float*)d_in[11];
    const float* bl0_iu = (const float*)d_in[12];
    const float* Wr0_iu = (const float*)d_in[13];
    const float* g0_u   = (const float*)d_in[14];
    const float* b0_u   = (const float*)d_in[15];
    const float* g0_i   = (const float*)d_in[16];
    const float* b0_i   = (const float*)d_in[17];
    const float* Wl1_ui = (const float*)d_in[18];
    const float* bl1_ui = (const float*)d_in[19];
    const float* Wr1_ui = (const float*)d_in[20];
    const float* Wl1_iu = (const float*)d_in[21];
    const float* bl1_iu = (const float*)d_in[22];
    const float* Wr1_iu = (const float*)d_in[23];
    const float* g1_u   = (const float*)d_in[24];
    const float* b1_u   = (const float*)d_in[25];
    const float* g1_i   = (const float*)d_in[26];
    const float* b1_i   = (const float*)d_in[27];

    float *hu, *hi, *aggu, *aggi, *hu1, *hi1, *wt;
    int *offu, *offi, *cntu, *cnti, *eix_ui, *eix_iu;
    cudaGetSymbolAddress((void**)&hu,   g_hu);
    cudaGetSymbolAddress((void**)&hi,   g_hi);
    cudaGetSymbolAddress((void**)&aggu, g_aggu);
    cudaGetSymbolAddress((void**)&aggi, g_aggi);
    cudaGetSymbolAddress((void**)&hu1,  g_hu1);
    cudaGetSymbolAddress((void**)&hi1,  g_hi1);
    cudaGetSymbolAddress((void**)&wt,   g_wt);
    cudaGetSymbolAddress((void**)&cntu, g_cntu);
    cudaGetSymbolAddress((void**)&cnti, g_cnti);
    cudaGetSymbolAddress((void**)&offu, g_offu);
    cudaGetSymbolAddress((void**)&offi, g_offi);
    cudaGetSymbolAddress((void**)&eix_ui, g_eidx_ui);
    cudaGetSymbolAddress((void**)&eix_iu, g_eidx_iu);

    float* out = (float*)d_out;

    float* wt_pu  = wt;             // 128 x 96
    float* wt_pi  = wt + 12288;     // 128 x 160
    float* wt0_ui = wt + 32768;     // 128 x 256
    float* wt0_iu = wt + 65536;     // 128 x 256
    float* wt1_iu = wt + 98304;     // 64 x 256
    float* wt1_ui = wt + 114688;    // 64 x 256

    const int SM_N128 = 3 * (128 * 32 * 4) + 3 * (128 * 32 * 4) + 3 * 128 * 4;  // 99840
    const int SM_N64  = 3 * (128 * 32 * 4) + 3 * (64 * 32 * 4)  + 3 * 64 * 4;   // 74496
    cudaFuncSetAttribute(proj_mma_kernel<FU_, HH>,
                         cudaFuncAttributeMaxDynamicSharedMemorySize, SM_N128);
    cudaFuncSetAttribute(proj_mma_kernel<FI_, HH>,
                         cudaFuncAttributeMaxDynamicSharedMemorySize, SM_N128);
    cudaFuncSetAttribute(sage_mma_kernel<HH, true>,
                         cudaFuncAttributeMaxDynamicSharedMemorySize, SM_N128);
    cudaFuncSetAttribute(sage_mma_kernel<OUTD, false>,
                         cudaFuncAttributeMaxDynamicSharedMemorySize, SM_N64);

    const int gblocks = (NU_ + 127) / 128;     // 782
    const int sblocks = (NU_ + 1023) / 1024;   // 98
    const int wblocks = (int)(((long long)NU_ * 32 + 255) / 256);

    // weight transposes + zero CSR counters (one kernel)
    transpose_all_kernel<<<(131072 + 255) / 256, 256>>>(
        Wp_u, Wp_i, Wl0_ui, Wr0_ui, Wl0_iu, Wr0_iu, Wl1_iu, Wr1_iu, Wl1_ui, Wr1_ui, wt);

    // CSR build (shared by both layers)
    count_kernel<<<(NE_ + 255) / 256, 256>>>(eui, eiu);
    scan1_kernel<<<dim3(sblocks, 2), 1024>>>(NU_);
    scan2_kernel<<<2, 128>>>(sblocks);
    scan3_kernel<<<dim3(sblocks, 2), 1024>>>(NU_);
    fill_kernel<<<(NE_ + 255) / 256, 256>>>(eui, eiu);

    // projections + relu
    proj_mma_kernel<FU_, HH><<<gblocks, 256, SM_N128>>>(x_user, wt_pu, bp_u, hu, NU_);
    proj_mma_kernel<FI_, HH><<<gblocks, 256, SM_N128>>>(x_item, wt_pi, bp_i, hi, NI_);

    // layer 0 aggregation (both sides, one launch; mean folded in)
    GatherArgs ga0;
    ga0.feat0 = hu; ga0.eidx0 = eix_ui; ga0.off0 = offi; ga0.cnt0 = cnti; ga0.agg0 = aggi;
    ga0.feat1 = hi; ga0.eidx1 = eix_iu; ga0.off1 = offu; ga0.cnt1 = cntu; ga0.agg1 = aggu;
    gather_kernel<<<dim3(wblocks, 2), 256>>>(ga0, NU_);

    // layer 0 SAGE + LN + relu (both sides, one launch)
    SageArgs a0;
    a0.agg0 = aggi; a0.root0 = hi; a0.wt0 = wt0_ui;
    a0.bias0 = bl0_ui; a0.gam0 = g0_i; a0.bet0 = b0_i; a0.y0 = hi1;
    a0.agg1 = aggu; a0.root1 = hu; a0.wt1 = wt0_iu;
    a0.bias1 = bl0_iu; a0.gam1 = g0_u; a0.bet1 = b0_u; a0.y1 = hu1;
    sage_mma_kernel<HH, true><<<dim3(gblocks, 2), 256, SM_N128>>>(a0, NU_);

    // layer 1 aggregation
    GatherArgs ga1;
    ga1.feat0 = hu1; ga1.eidx0 = eix_ui; ga1.off0 = offi; ga1.cnt0 = cnti; ga1.agg0 = aggi;
    ga1.feat1 = hi1; ga1.eidx1 = eix_iu; ga1.off1 = offu; ga1.cnt1 = cntu; ga1.agg1 = aggu;
    gather_kernel<<<dim3(wblocks, 2), 256>>>(ga1, NU_);

    // layer 1 SAGE + LN (no relu); outputs [h_u2 | h_i2]
    SageArgs a1;
    a1.agg0 = aggi; a1.root0 = hi1; a1.wt0 = wt1_ui;
    a1.bias0 = bl1_ui; a1.gam0 = g1_i; a1.bet0 = b1_i; a1.y0 = out + (size_t)NU_ * OUTD;
    a1.agg1 = aggu; a1.root1 = hu1; a1.wt1 = wt1_iu;
    a1.bias1 = bl1_iu; a1.gam1 = g1_u; a1.bet1 = b1_u; a1.y1 = out;
    sage_mma_kernel<OUTD, false><<<dim3(gblocks, 2), 256, SM_N64>>>(a1, NU_);
}

// round 16
// speedup vs baseline: 1.1254x; 1.0095x over previous
#include <cuda_runtime.h>
#include <cstdint>

#define NU_  100000
#define NI_  100000
#define NE_  600000
#define FU_  96
#define FI_  160
#define HH   128
#define OUTD 64
#define LN_EPS 1e-5f

// ---------------- scratch (device globals; no runtime allocation) ----------------
__device__ float g_hu  [NU_ * HH];
__device__ float g_hi  [NI_ * HH];
__device__ float g_aggu[NU_ * HH];
__device__ float g_aggi[NI_ * HH];
__device__ float g_hu1 [NU_ * HH];
__device__ float g_hi1 [NI_ * HH];
__device__ int   g_cntu[NU_];
__device__ int   g_cnti[NI_];
__device__ int   g_offu[NU_];
__device__ int   g_offi[NI_];
__device__ int   g_curu[NU_];
__device__ int   g_curi[NI_];
__device__ int   g_runu;
__device__ int   g_runi;
__device__ int   g_eidx_ui[NE_];   // src user idx, grouped by dst item
__device__ int   g_eidx_iu[NE_];   // src item idx, grouped by dst user
__device__ float g_wt[131072];     // transposed weights

// ---------------- small helpers ----------------
__device__ __forceinline__ uint32_t smem_u32(const void* p) {
    uint32_t a;
    asm("{ .reg .u64 t; cvta.to.shared.u64 t, %1; cvt.u32.u64 %0, t; }" : "=r"(a) : "l"(p));
    return a;
}

// ---------------- CSR build ----------------
__global__ void count_kernel(const int* __restrict__ eui, const int* __restrict__ eiu) {
    int e = blockIdx.x * blockDim.x + threadIdx.x;
    if (e < NE_) {
        atomicAdd(&g_cnti[eui[NE_ + e]], 1);
        atomicAdd(&g_cntu[eiu[NE_ + e]], 1);
    }
}

// single-pass scan: block-local scan + atomic-ordered global base (y selects u/i)
__global__ void scan_onepass_kernel(int n) {
    const int* cnt = blockIdx.y ? g_cnti : g_cntu;
    int* off = blockIdx.y ? g_offi : g_offu;
    int* cur = blockIdx.y ? g_curi : g_curu;
    int* run = blockIdx.y ? &g_runi : &g_runu;
    __shared__ int s[1024];
    __shared__ int sbase;
    int t = threadIdx.x, i = blockIdx.x * 1024 + t;
    int v = (i < n) ? cnt[i] : 0;
    s[t] = v;
    __syncthreads();
#pragma unroll
    for (int d = 1; d < 1024; d <<= 1) {
        int y = (t >= d) ? s[t - d] : 0;
        __syncthreads();
        s[t] += y;
        __syncthreads();
    }
    if (t == 1023) sbase = atomicAdd(run, s[1023]);
    __syncthreads();
    if (i < n) {
        int o = sbase + s[t] - v;
        off[i] = o;
        cur[i] = o;
    }
}

__global__ void fill_kernel(const int* __restrict__ eui, const int* __restrict__ eiu) {
    int e = blockIdx.x * blockDim.x + threadIdx.x;
    if (e < NE_) {
        int di = eui[NE_ + e];
        int p  = atomicAdd(&g_curi[di], 1);
        g_eidx_ui[p] = eui[e];
        int du = eiu[NE_ + e];
        int p2 = atomicAdd(&g_curu[du], 1);
        g_eidx_iu[p2] = eiu[e];
    }
}

// ---------------- dual gather-mean aggregation: warp per destination row ----------------
struct GatherArgs {
    const float* feat0; const int* eidx0; const int* off0; const int* cnt0; float* agg0;
    const float* feat1; const int* eidx1; const int* off1; const int* cnt1; float* agg1;
};

__global__ void gather_kernel(GatherArgs a, int n) {
    const float* feat = blockIdx.y ? a.feat1 : a.feat0;
    const int* eidx   = blockIdx.y ? a.eidx1 : a.eidx0;
    const int* off    = blockIdx.y ? a.off1  : a.off0;
    const int* cnt    = blockIdx.y ? a.cnt1  : a.cnt0;
    float* agg        = blockIdx.y ? a.agg1  : a.agg0;
    int gw = (int)(((long long)blockIdx.x * blockDim.x + threadIdx.x) >> 5);
    if (gw >= n) return;
    int lane = threadIdx.x & 31;
    int start = off[gw], c = cnt[gw];
    float4 a0 = make_float4(0.f, 0.f, 0.f, 0.f);
    float4 a1 = make_float4(0.f, 0.f, 0.f, 0.f);
    int j = 0;
    for (; j + 2 <= c; j += 2) {
        int s0 = __ldg(&eidx[start + j]);
        int s1 = __ldg(&eidx[start + j + 1]);
        float4 v0 = *(const float4*)(feat + (size_t)s0 * HH + lane * 4);
        float4 v1 = *(const float4*)(feat + (size_t)s1 * HH + lane * 4);
        a0.x += v0.x; a0.y += v0.y; a0.z += v0.z; a0.w += v0.w;
        a1.x += v1.x; a1.y += v1.y; a1.z += v1.z; a1.w += v1.w;
    }
    if (j < c) {
        int s0 = __ldg(&eidx[start + j]);
        float4 v0 = *(const float4*)(feat + (size_t)s0 * HH + lane * 4);
        a0.x += v0.x; a0.y += v0.y; a0.z += v0.z; a0.w += v0.w;
    }
    float sc = 1.f / (float)max(c, 1);
    float4 r = make_float4((a0.x + a1.x) * sc, (a0.y + a1.y) * sc,
                           (a0.z + a1.z) * sc, (a0.w + a1.w) * sc);
    *(float4*)(agg + (size_t)gw * HH + lane * 4) = r;
}

// ---------------- weight transposes (+ zero the CSR counters) ----------------
// regions in g_wt: [0) pu 128x96 | [12288) pi 128x160 | [32768) ui0 128x256 |
//                  [65536) iu0 128x256 | [98304) iu1 64x256 | [114688) ui1 64x256
__global__ void transpose_all_kernel(
    const float* __restrict__ Wp_u, const float* __restrict__ Wp_i,
    const float* __restrict__ Wl0_ui, const float* __restrict__ Wr0_ui,
    const float* __restrict__ Wl0_iu, const float* __restrict__ Wr0_iu,
    const float* __restrict__ Wl1_iu, const float* __restrict__ Wr1_iu,
    const float* __restrict__ Wl1_ui, const float* __restrict__ Wr1_ui,
    float* __restrict__ dst) {
    int idx = blockIdx.x * blockDim.x + threadIdx.x;
    if (idx < NU_) { g_cntu[idx] = 0; g_cnti[idx] = 0; }
    if (idx == 0) { g_runu = 0; g_runi = 0; }
    if (idx >= 131072) return;
    const float *W1, *W2; int K1, KTOT, NOUT, li;
    if (idx < 12288)       { li = idx;          W1 = Wp_u;   W2 = Wp_u;   K1 = 96;  KTOT = 96;  NOUT = 128; }
    else if (idx < 32768)  { li = idx - 12288;  W1 = Wp_i;   W2 = Wp_i;   K1 = 160; KTOT = 160; NOUT = 128; }
    else if (idx < 65536)  { li = idx - 32768;  W1 = Wl0_ui; W2 = Wr0_ui; K1 = 128; KTOT = 256; NOUT = 128; }
    else if (idx < 98304)  { li = idx - 65536;  W1 = Wl0_iu; W2 = Wr0_iu; K1 = 128; KTOT = 256; NOUT = 128; }
    else if (idx < 114688) { li = idx - 98304;  W1 = Wl1_iu; W2 = Wr1_iu; K1 = 128; KTOT = 256; NOUT = 64;  }
    else                   { li = idx - 114688; W1 = Wl1_ui; W2 = Wr1_ui; K1 = 128; KTOT = 256; NOUT = 64;  }
    int n = li / KTOT, k = li % KTOT;
    dst[idx] = (k < K1) ? W1[(size_t)k * NOUT + n] : W2[(size_t)(k - K1) * NOUT + n];
}

// ======================= tf32 mma GEMM core (2-buffer, R11-proven) =======================
// block: 256 thr = 8 warps, 128 rows; warp: m16 x NOUT; K chunks of 32, double-buffered.
template <int NOUT>
struct MmaCore {
    static constexpr int NT = NOUT / 8;
    static constexpr int ABUF = 128 * 32 * 4;
    static constexpr int BBUF = NOUT * 32 * 4;

    uint32_t sb; int tid, w, lane;

    __device__ __forceinline__ void stageA_row(const float* src, int rowlen, int ak,
                                               int c, int base, int nrows) {
        uint32_t aB = sb + (c & 1) * ABUF;
#pragma unroll
        for (int t = 0; t < 4; t++) {
            int slot = tid + t * 256;
            int r = slot >> 3, j = slot & 7;
            int gr = base + r;
            const float* s = src + (size_t)gr * rowlen + ak + j * 4;
            uint32_t dst = aB + r * 128 + ((j ^ (r & 7)) << 4);
            int sz = (gr < nrows) ? 16 : 0;
            asm volatile("cp.async.cg.shared.global [%0], [%1], 16, %2;"
                         :: "r"(dst), "l"(s), "r"(sz));
        }
    }
    __device__ __forceinline__ void stageB(const float* Wt, int ktot, int c) {
        uint32_t bB = sb + 2 * ABUF + (c & 1) * BBUF;
#pragma unroll
        for (int t = 0; t < NOUT / 32; t++) {
            int slot = tid + t * 256;
            int n = slot >> 3, j = slot & 7;
            const float* s = Wt + (size_t)n * ktot + c * 32 + j * 4;
            uint32_t dst = bB + n * 128 + ((j ^ (n & 7)) << 4);
            asm volatile("cp.async.cg.shared.global [%0], [%1], 16;"
                         :: "r"(dst), "l"(s));
        }
    }
    __device__ __forceinline__ void compute(int c, float (*acc)[4]) {
        uint32_t aB = sb + (c & 1) * ABUF;
        uint32_t bB = sb + 2 * ABUF + (c & 1) * BBUF;
#pragma unroll
        for (int kk = 0; kk < 4; kk++) {
            uint32_t a0, a1, a2, a3;
            {
                int m = lane >> 3, i = lane & 7;
                int row = w * 16 + (m & 1) * 8 + i;
                int j = kk * 2 + (m >> 1);
                uint32_t addr = aB + row * 128 + ((j ^ (row & 7)) << 4);
                asm volatile("ldmatrix.sync.aligned.m8n8.x4.shared.b16 {%0,%1,%2,%3}, [%4];"
                             : "=r"(a0), "=r"(a1), "=r"(a2), "=r"(a3) : "r"(addr));
            }
#pragma unroll
            for (int p = 0; p < NT / 2; p++) {
                uint32_t b0, b1, b2, b3;
                {
                    int m = lane >> 3, i = lane & 7;
                    int nrow = p * 16 + (m >> 1) * 8 + i;
                    int j = kk * 2 + (m & 1);
                    uint32_t addr = bB + nrow * 128 + ((j ^ (nrow & 7)) << 4);
                    asm volatile("ldmatrix.sync.aligned.m8n8.x4.shared.b16 {%0,%1,%2,%3}, [%4];"
                                 : "=r"(b0), "=r"(b1), "=r"(b2), "=r"(b3) : "r"(addr));
                }
                asm volatile(
                    "mma.sync.aligned.m16n8k8.row.col.f32.tf32.tf32.f32 "
                    "{%0,%1,%2,%3}, {%4,%5,%6,%7}, {%8,%9}, {%0,%1,%2,%3};"
                    : "+f"(acc[2 * p][0]), "+f"(acc[2 * p][1]), "+f"(acc[2 * p][2]), "+f"(acc[2 * p][3])
                    : "r"(a0), "r"(a1), "r"(a2), "r"(a3), "r"(b0), "r"(b1));
                asm volatile(
                    "mma.sync.aligned.m16n8k8.row.col.f32.tf32.tf32.f32 "
                    "{%0,%1,%2,%3}, {%4,%5,%6,%7}, {%8,%9}, {%0,%1,%2,%3};"
                    : "+f"(acc[2 * p + 1][0]), "+f"(acc[2 * p + 1][1]), "+f"(acc[2 * p + 1][2]), "+f"(acc[2 * p + 1][3])
                    : "r"(a0), "r"(a1), "r"(a2), "r"(a3), "r"(b2), "r"(b3));
            }
        }
    }
};

// ---------------- dual projection GEMM: y = relu(X @ Wp + b), runtime K ----------------
struct ProjArgs {
    const float* A0; const float* Wt0; const float* b0; float* y0; int K0;
    const float* A1; const float* Wt1; const float* b1; float* y1; int K1;
};

__global__ void __launch_bounds__(256) proj_mma_kernel(ProjArgs pa, int nrows)
{
    constexpr int NOUT = HH;
    constexpr int NT = NOUT / 8;
    using Core = MmaCore<NOUT>;
    extern __shared__ __align__(128) char smem[];
    float* s_bias = (float*)(smem + 2 * Core::ABUF + 2 * Core::BBUF);

    int side = blockIdx.y;
    const float* A    = side ? pa.A1  : pa.A0;
    const float* Wt   = side ? pa.Wt1 : pa.Wt0;
    const float* bias = side ? pa.b1  : pa.b0;
    float* y          = side ? pa.y1  : pa.y0;
    const int KTOT    = side ? pa.K1  : pa.K0;
    const int NC = KTOT / 32;

    Core core;
    core.sb = smem_u32(smem);
    core.tid = threadIdx.x;
    core.w = threadIdx.x >> 5;
    core.lane = threadIdx.x & 31;
    int g = core.lane >> 2, tig = core.lane & 3;
    int base = blockIdx.x * 128;

    if (core.tid < NOUT) s_bias[core.tid] = bias[core.tid];

    float acc[NT][4];
#pragma unroll
    for (int nt = 0; nt < NT; nt++)
#pragma unroll
        for (int q = 0; q < 4; q++) acc[nt][q] = 0.f;

    auto stage = [&](int c) {
        core.stageA_row(A, KTOT, c * 32, c, base, nrows);
        core.stageB(Wt, KTOT, c);
        asm volatile("cp.async.commit_group;" ::: "memory");
    };

    stage(0);
    for (int c = 0; c < NC; c++) {
        if (c + 1 < NC) {
            stage(c + 1);
            asm volatile("cp.async.wait_group 1;" ::: "memory");
        } else {
            asm volatile("cp.async.wait_group 0;" ::: "memory");
        }
        __syncthreads();
        core.compute(c, acc);
        __syncthreads();
    }

    int r0 = base + core.w * 16 + g;
    int r1 = r0 + 8;
    if (r0 < nrows) {
        float* yr = y + (size_t)r0 * NOUT;
#pragma unroll
        for (int nt = 0; nt < NT; nt++) {
            int cb = nt * 8 + tig * 2;
            float o0 = fmaxf(acc[nt][0] + s_bias[cb], 0.f);
            float o1 = fmaxf(acc[nt][1] + s_bias[cb + 1], 0.f);
            *(float2*)(yr + cb) = make_float2(o0, o1);
        }
    }
    if (r1 < nrows) {
        float* yr = y + (size_t)r1 * NOUT;
#pragma unroll
        for (int nt = 0; nt < NT; nt++) {
            int cb = nt * 8 + tig * 2;
            float o0 = fmaxf(acc[nt][2] + s_bias[cb], 0.f);
            float o1 = fmaxf(acc[nt][3] + s_bias[cb + 1], 0.f);
            *(float2*)(yr + cb) = make_float2(o0, o1);
        }
    }
}

// ---------------- dual SAGE GEMM + LN (+ReLU): y = LN([agg|root] @ Wt^T + b) ----------------
struct SageArgs {
    const float* agg0; const float* root0; const float* wt0;
    const float* bias0; const float* gam0; const float* bet0; float* y0;
    const float* agg1; const float* root1; const float* wt1;
    const float* bias1; const float* gam1; const float* bet1; float* y1;
};

template <int NOUT, bool RELU>
__global__ void __launch_bounds__(256) sage_mma_kernel(SageArgs a, int nrows)
{
    constexpr int NT = NOUT / 8;
    constexpr int NC = 8;   // K = 256
    using Core = MmaCore<NOUT>;
    extern __shared__ __align__(128) char smem[];
    float* s_bias = (float*)(smem + 2 * Core::ABUF + 2 * Core::BBUF);
    float* s_g    = s_bias + NOUT;
    float* s_be   = s_g + NOUT;

    int side = blockIdx.y;
    const float* agg  = side ? a.agg1  : a.agg0;
    const float* root = side ? a.root1 : a.root0;
    const float* Wt   = side ? a.wt1   : a.wt0;
    const float* bias = side ? a.bias1 : a.bias0;
    const float* gam  = side ? a.gam1  : a.gam0;
    const float* bet  = side ? a.bet1  : a.bet0;
    float* y          = side ? a.y1    : a.y0;

    Core core;
    core.sb = smem_u32(smem);
    core.tid = threadIdx.x;
    core.w = threadIdx.x >> 5;
    core.lane = threadIdx.x & 31;
    int g = core.lane >> 2, tig = core.lane & 3;
    int base = blockIdx.x * 128;

    if (core.tid < NOUT) {
        s_bias[core.tid] = bias[core.tid];
        s_g[core.tid] = gam[core.tid];
        s_be[core.tid] = bet[core.tid];
    }

    float acc[NT][4];
#pragma unroll
    for (int nt = 0; nt < NT; nt++)
#pragma unroll
        for (int q = 0; q < 4; q++) acc[nt][q] = 0.f;

    auto stage = [&](int c) {
        if (c < 4) core.stageA_row(agg,  HH, c * 32,       c, base, nrows);
        else       core.stageA_row(root, HH, (c - 4) * 32, c, base, nrows);
        core.stageB(Wt, 256, c);
        asm volatile("cp.async.commit_group;" ::: "memory");
    };

    stage(0);
    for (int c = 0; c < NC; c++) {
        if (c + 1 < NC) {
            stage(c + 1);
            asm volatile("cp.async.wait_group 1;" ::: "memory");
        } else {
            asm volatile("cp.async.wait_group 0;" ::: "memory");
        }
        __syncthreads();
        core.compute(c, acc);
        __syncthreads();
    }

    // ---- epilogue: bias + LN (+ReLU) ----
    int r0 = base + core.w * 16 + g;
    int r1 = r0 + 8;

#pragma unroll
    for (int nt = 0; nt < NT; nt++) {
        int cb = nt * 8 + tig * 2;
        float b0f = s_bias[cb], b1f = s_bias[cb + 1];
        acc[nt][0] += b0f; acc[nt][1] += b1f;
        acc[nt][2] += b0f; acc[nt][3] += b1f;
    }

    float s0 = 0.f, q0 = 0.f, s1 = 0.f, q1 = 0.f;
#pragma unroll
    for (int nt = 0; nt < NT; nt++) {
        s0 += acc[nt][0] + acc[nt][1];
        q0 += acc[nt][0] * acc[nt][0] + acc[nt][1] * acc[nt][1];
        s1 += acc[nt][2] + acc[nt][3];
        q1 += acc[nt][2] * acc[nt][2] + acc[nt][3] * acc[nt][3];
    }
#pragma unroll
    for (int m = 1; m <= 2; m <<= 1) {
        s0 += __shfl_xor_sync(0xffffffffu, s0, m);
        q0 += __shfl_xor_sync(0xffffffffu, q0, m);
        s1 += __shfl_xor_sync(0xffffffffu, s1, m);
        q1 += __shfl_xor_sync(0xffffffffu, q1, m);
    }
    float mean0 = s0 / (float)NOUT;
    float mean1 = s1 / (float)NOUT;
    float rs0 = rsqrtf(q0 / (float)NOUT - mean0 * mean0 + LN_EPS);
    float rs1 = rsqrtf(q1 / (float)NOUT - mean1 * mean1 + LN_EPS);

    if (r0 < nrows) {
        float* yr = y + (size_t)r0 * NOUT;
#pragma unroll
        for (int nt = 0; nt < NT; nt++) {
            int cb = nt * 8 + tig * 2;
            float o0 = (acc[nt][0] - mean0) * rs0 * s_g[cb]     + s_be[cb];
            float o1 = (acc[nt][1] - mean0) * rs0 * s_g[cb + 1] + s_be[cb + 1];
            if (RELU) { o0 = fmaxf(o0, 0.f); o1 = fmaxf(o1, 0.f); }
            *(float2*)(yr + cb) = make_float2(o0, o1);
        }
    }
    if (r1 < nrows) {
        float* yr = y + (size_t)r1 * NOUT;
#pragma unroll
        for (int nt = 0; nt < NT; nt++) {
            int cb = nt * 8 + tig * 2;
            float o0 = (acc[nt][2] - mean1) * rs1 * s_g[cb]     + s_be[cb];
            float o1 = (acc[nt][3] - mean1) * rs1 * s_g[cb + 1] + s_be[cb + 1];
            if (RELU) { o0 = fmaxf(o0, 0.f); o1 = fmaxf(o1, 0.f); }
            *(float2*)(yr + cb) = make_float2(o0, o1);
        }
    }
}

// ---------------- launcher ----------------
extern "C" void kernel_launch(void* const* d_in, const int* in_sizes, int n_in,
                              void* d_out, int out_size) {
    (void)in_sizes; (void)n_in; (void)out_size;
    const float* x_user = (const float*)d_in[0];
    const float* x_item = (const float*)d_in[1];
    const int*   eui    = (const int*)d_in[2];
    const int*   eiu    = (const int*)d_in[3];
    const float* Wp_u   = (const float*)d_in[4];
    const float* bp_u   = (const float*)d_in[5];
    const float* Wp_i   = (const float*)d_in[6];
    const float* bp_i   = (const float*)d_in[7];
    const float* Wl0_ui = (const float*)d_in[8];
    const float* bl0_ui = (const float*)d_in[9];
    const float* Wr0_ui = (const float*)d_in[10];
    const float* Wl0_iu = (const float*)d_in[11];
    const float* bl0_iu = (const float*)d_in[12];
    const float* Wr0_iu = (const float*)d_in[13];
    const float* g0_u   = (const float*)d_in[14];
    const float* b0_u   = (const float*)d_in[15];
    const float* g0_i   = (const float*)d_in[16];
    const float* b0_i   = (const float*)d_in[17];
    const float* Wl1_ui = (const float*)d_in[18];
    const float* bl1_ui = (const float*)d_in[19];
    const float* Wr1_ui = (const float*)d_in[20];
    const float* Wl1_iu = (const float*)d_in[21];
    const float* bl1_iu = (const float*)d_in[22];
    const float* Wr1_iu = (const float*)d_in[23];
    const float* g1_u   = (const float*)d_in[24];
    const float* b1_u   = (const float*)d_in[25];
    const float* g1_i   = (const float*)d_in[26];
    const float* b1_i   = (const float*)d_in[27];

    float *hu, *hi, *aggu, *aggi, *hu1, *hi1, *wt;
    int *offu, *offi, *cntu, *cnti, *eix_ui, *eix_iu;
    cudaGetSymbolAddress((void**)&hu,   g_hu);
    cudaGetSymbolAddress((void**)&hi,   g_hi);
    cudaGetSymbolAddress((void**)&aggu, g_aggu);
    cudaGetSymbolAddress((void**)&aggi, g_aggi);
    cudaGetSymbolAddress((void**)&hu1,  g_hu1);
    cudaGetSymbolAddress((void**)&hi1,  g_hi1);
    cudaGetSymbolAddress((void**)&wt,   g_wt);
    cudaGetSymbolAddress((void**)&cntu, g_cntu);
    cudaGetSymbolAddress((void**)&cnti, g_cnti);
    cudaGetSymbolAddress((void**)&offu, g_offu);
    cudaGetSymbolAddress((void**)&offi, g_offi);
    cudaGetSymbolAddress((void**)&eix_ui, g_eidx_ui);
    cudaGetSymbolAddress((void**)&eix_iu, g_eidx_iu);

    float* out = (float*)d_out;

    float* wt_pu  = wt;             // 128 x 96
    float* wt_pi  = wt + 12288;     // 128 x 160
    float* wt0_ui = wt + 32768;     // 128 x 256
    float* wt0_iu = wt + 65536;     // 128 x 256
    float* wt1_iu = wt + 98304;     // 64 x 256
    float* wt1_ui = wt + 114688;    // 64 x 256

    const int SM_PROJ = 2 * (128 * 32 * 4) + 2 * (128 * 32 * 4) + 128 * 4;      // 66048
    const int SM_S128 = 2 * (128 * 32 * 4) + 2 * (128 * 32 * 4) + 3 * 128 * 4;  // 67072
    const int SM_S64  = 2 * (128 * 32 * 4) + 2 * (64 * 32 * 4)  + 3 * 64 * 4;   // 49920
    cudaFuncSetAttribute(proj_mma_kernel,
                         cudaFuncAttributeMaxDynamicSharedMemorySize, SM_PROJ);
    cudaFuncSetAttribute(sage_mma_kernel<HH, true>,
                         cudaFuncAttributeMaxDynamicSharedMemorySize, SM_S128);
    cudaFuncSetAttribute(sage_mma_kernel<OUTD, false>,
                         cudaFuncAttributeMaxDynamicSharedMemorySize, SM_S64);

    const int gblocks = (NU_ + 127) / 128;     // 782
    const int sblocks = (NU_ + 1023) / 1024;   // 98
    const int wblocks = (int)(((long long)NU_ * 32 + 255) / 256);

    // weight transposes + zero CSR counters (one kernel)
    transpose_all_kernel<<<(131072 + 255) / 256, 256>>>(
        Wp_u, Wp_i, Wl0_ui, Wr0_ui, Wl0_iu, Wr0_iu, Wl1_iu, Wr1_iu, Wl1_ui, Wr1_ui, wt);

    // CSR build (shared by both layers): count -> one-pass scan -> fill
    count_kernel<<<(NE_ + 255) / 256, 256>>>(eui, eiu);
    scan_onepass_kernel<<<dim3(sblocks, 2), 1024>>>(NU_);
    fill_kernel<<<(NE_ + 255) / 256, 256>>>(eui, eiu);

    // projections + relu (both types, one launch)
    ProjArgs pa;
    pa.A0 = x_user; pa.Wt0 = wt_pu; pa.b0 = bp_u; pa.y0 = hu; pa.K0 = FU_;
    pa.A1 = x_item; pa.Wt1 = wt_pi; pa.b1 = bp_i; pa.y1 = hi; pa.K1 = FI_;
    proj_mma_kernel<<<dim3(gblocks, 2), 256, SM_PROJ>>>(pa, NU_);

    // layer 0 aggregation (both sides, one launch; mean folded in)
    GatherArgs ga0;
    ga0.feat0 = hu; ga0.eidx0 = eix_ui; ga0.off0 = offi; ga0.cnt0 = cnti; ga0.agg0 = aggi;
    ga0.feat1 = hi; ga0.eidx1 = eix_iu; ga0.off1 = offu; ga0.cnt1 = cntu; ga0.agg1 = aggu;
    gather_kernel<<<dim3(wblocks, 2), 256>>>(ga0, NU_);

    // layer 0 SAGE + LN + relu (both sides, one launch)
    SageArgs a0;
    a0.agg0 = aggi; a0.root0 = hi; a0.wt0 = wt0_ui;
    a0.bias0 = bl0_ui; a0.gam0 = g0_i; a0.bet0 = b0_i; a0.y0 = hi1;
    a0.agg1 = aggu; a0.root1 = hu; a0.wt1 = wt0_iu;
    a0.bias1 = bl0_iu; a0.gam1 = g0_u; a0.bet1 = b0_u; a0.y1 = hu1;
    sage_mma_kernel<HH, true><<<dim3(gblocks, 2), 256, SM_S128>>>(a0, NU_);

    // layer 1 aggregation
    GatherArgs ga1;
    ga1.feat0 = hu1; ga1.eidx0 = eix_ui; ga1.off0 = offi; ga1.cnt0 = cnti; ga1.agg0 = aggi;
    ga1.feat1 = hi1; ga1.eidx1 = eix_iu; ga1.off1 = offu; ga1.cnt1 = cntu; ga1.agg1 = aggu;
    gather_kernel<<<dim3(wblocks, 2), 256>>>(ga1, NU_);

    // layer 1 SAGE + LN (no relu); outputs [h_u2 | h_i2]
    SageArgs a1;
    a1.agg0 = aggi; a1.root0 = hi1; a1.wt0 = wt1_ui;
    a1.bias0 = bl1_ui; a1.gam0 = g1_i; a1.bet0 = b1_i; a1.y0 = out + (size_t)NU_ * OUTD;
    a1.agg1 = aggu; a1.root1 = hu1; a1.wt1 = wt1_iu;
    a1.bias1 = bl1_iu; a1.gam1 = g1_u; a1.bet1 = b1_u; a1.y1 = out;
    sage_mma_kernel<OUTD, false><<<dim3(gblocks, 2), 256, SM_S64>>>(a1, NU_);
}